// round 16
// baseline (speedup 1.0000x reference)
#include <cuda_runtime.h>
#include <cstdint>

// Problem constants
#define DEPTH 2
#define NEXP  16
#define HDIM  1024
#define NTOK  8192
#define CAP   4096      // per-expert slot capacity (mean occupancy 1024)

// GEMM tile config
#define BM 128
#define BN 128
#define KC 32           // K floats per chunk (128B rows)
#define NTHREADS 256
#define LDS_PAD 36      // smem row stride in floats; bank=(4*gid+tg)%32 conflict-free

// ---------------------------------------------------------------------------
// Device-global scratch (no allocations allowed in kernel_launch)
// ---------------------------------------------------------------------------
__device__ float g_act[(size_t)NTOK * HDIM];          // layer-0 output activations
__device__ float g_pair[(size_t)NTOK * 2 * HDIM];     // per-assignment expert outputs
__device__ int   g_cnt[NEXP];
__device__ int   g_tok[NEXP * CAP];                   // packed token*2 + k
__device__ float g_wt[NEXP * CAP];                    // softmax gate weight per assignment

// ---------------------------------------------------------------------------
// Small PTX helpers
// ---------------------------------------------------------------------------
__device__ __forceinline__ uint32_t f2tf(float x) {
    uint32_t u;
    asm("cvt.rna.tf32.f32 %0, %1;" : "=r"(u) : "f"(x));
    return u;
}

// tf32x3 split: v = hi + lo (hi = rna.tf32(v); lo = rna.tf32(v - hi)).
__device__ __forceinline__ void f2tf_pair(float v, uint32_t& hi, uint32_t& lo) {
    hi = f2tf(v);
    lo = f2tf(v - __uint_as_float(hi));
}

__device__ __forceinline__ void mma_tf32(float* d, const uint32_t* a, const uint32_t* b) {
    asm volatile(
        "mma.sync.aligned.m16n8k8.row.col.f32.tf32.tf32.f32 "
        "{%0,%1,%2,%3}, {%4,%5,%6,%7}, {%8,%9}, {%0,%1,%2,%3};"
        : "+f"(d[0]), "+f"(d[1]), "+f"(d[2]), "+f"(d[3])
        : "r"(a[0]), "r"(a[1]), "r"(a[2]), "r"(a[3]), "r"(b[0]), "r"(b[1]));
}

__device__ __forceinline__ void cp16(uint32_t smem_dst, const void* gsrc) {
    asm volatile("cp.async.cg.shared.global [%0], [%1], 16;" :: "r"(smem_dst), "l"(gsrc));
}
__device__ __forceinline__ void cp_commit() { asm volatile("cp.async.commit_group;"); }
__device__ __forceinline__ void cp_wait1()  { asm volatile("cp.async.wait_group 1;"); }
__device__ __forceinline__ void cp_wait0()  { asm volatile("cp.async.wait_group 0;"); }

// ---------------------------------------------------------------------------
// Kernel 0: reset per-expert counters (per layer)
// ---------------------------------------------------------------------------
__global__ void reset_kernel() {
    if (threadIdx.x < NEXP) g_cnt[threadIdx.x] = 0;
}

// ---------------------------------------------------------------------------
// Kernel 1: gating — logits (fp32 FFMA), top-2, softmax, routing lists.
// ---------------------------------------------------------------------------
__global__ __launch_bounds__(256) void gate_kernel(
    int layer,
    const float* __restrict__ Xext,
    const float* __restrict__ gw,   // layer-offset: [NEXP, HDIM]
    const float* __restrict__ gb)   // layer-offset: [NEXP]
{
    const float* x = (layer == 0) ? Xext : g_act;

    __shared__ float4 sx4[8 * (HDIM / 4)];   // 8 tokens x 256 float4 = 32 KB

    int tid = threadIdx.x;
    const float4* x4 = reinterpret_cast<const float4*>(x);
    #pragma unroll
    for (int i = tid; i < 8 * (HDIM / 4); i += 256)
        sx4[i] = x4[(size_t)blockIdx.x * (8 * HDIM / 4) + i];
    __syncthreads();

    int wid  = tid >> 5;
    int lane = tid & 31;
    int b    = blockIdx.x * 8 + wid;

    const float4* gw4 = reinterpret_cast<const float4*>(gw);
    float G[NEXP];
    #pragma unroll
    for (int e = 0; e < NEXP; e++) {
        float acc = 0.f;
        #pragma unroll
        for (int j = 0; j < 8; j++) {
            float4 xv = sx4[wid * 256 + j * 32 + lane];
            float4 wv = gw4[e * 256 + j * 32 + lane];
            acc += xv.x * wv.x + xv.y * wv.y + xv.z * wv.z + xv.w * wv.w;
        }
        #pragma unroll
        for (int off = 16; off; off >>= 1)
            acc += __shfl_xor_sync(0xFFFFFFFFu, acc, off);
        G[e] = acc + gb[e];
    }

    if (lane == 0) {
        // top-2 with lowest-index tie-break (strict >), matching jax top_k
        int e0 = 0;
        #pragma unroll
        for (int e = 1; e < NEXP; e++) if (G[e] > G[e0]) e0 = e;
        int e1 = (e0 == 0) ? 1 : 0;
        #pragma unroll
        for (int e = 0; e < NEXP; e++) if (e != e0 && G[e] > G[e1]) e1 = e;

        float v0 = G[e0], v1 = G[e1];
        float z1 = expf(v1 - v0);          // v0 >= v1 -> stable
        float s  = 1.f + z1;
        float w0 = 1.f / s;
        float w1 = z1 / s;

        int p0 = atomicAdd(&g_cnt[e0], 1);
        if (p0 < CAP) { g_tok[e0 * CAP + p0] = b * 2 + 0; g_wt[e0 * CAP + p0] = w0; }
        int p1 = atomicAdd(&g_cnt[e1], 1);
        if (p1 < CAP) { g_tok[e1 * CAP + p1] = b * 2 + 1; g_wt[e1 * CAP + p1] = w1; }
    }
}

// ---------------------------------------------------------------------------
// Kernel 2: grouped expert GEMM (tf32x3 / tf32x2 mma.sync)
//           + bias + PReLU + gate weight epilogue.
// sweeps3=1: hi*hi + lo*hi + hi*lo (fp32-grade; layer feeding routing)
// sweeps3=0: hi*hi + lo*hi          (~2.4e-4 rel; final layer)
// ---------------------------------------------------------------------------
__device__ __forceinline__ void load_tiles(
    const float* __restrict__ xin, const float* __restrict__ W,
    const int* s_tok, float (*As)[LDS_PAD], float (*Bs)[LDS_PAD],
    int n_base, int k0, int tid)
{
    #pragma unroll
    for (int it = 0; it < 4; it++) {
        int q   = tid + it * 256;          // 0..1023
        int row = q >> 3;                  // 0..127
        int cc  = (q & 7) * 4;             // 0..28
        const float* asrc = xin + (size_t)(s_tok[row] >> 1) * HDIM + k0 + cc;
        cp16((uint32_t)__cvta_generic_to_shared(&As[row][cc]), asrc);
        const float* bsrc = W + (size_t)(n_base + row) * HDIM + k0 + cc;
        cp16((uint32_t)__cvta_generic_to_shared(&Bs[row][cc]), bsrc);
    }
}

__global__ __launch_bounds__(NTHREADS, 1) void expert_gemm_kernel(
    int layer, int sweeps3,
    const float* __restrict__ Xext,
    const float* __restrict__ ew,   // layer-offset: [NEXP, HDIM, HDIM] (o,i)
    const float* __restrict__ eb,   // layer-offset: [NEXP, HDIM]
    const float* __restrict__ pl,
    const float* __restrict__ pr,
    const float* __restrict__ pp,
    const float* __restrict__ pb)
{
    int e      = blockIdx.z;
    int m_base = blockIdx.y * BM;
    int n_base = blockIdx.x * BN;

    int cnt = g_cnt[e];
    if (cnt > CAP) cnt = CAP;
    if (m_base >= cnt) return;

    const float* xin = (layer == 0) ? Xext : g_act;
    const float* W   = ew + (size_t)e * HDIM * HDIM;

    __shared__ float As[2][BM][LDS_PAD];
    __shared__ float Bs[2][BN][LDS_PAD];
    __shared__ int   s_tok[BM];
    __shared__ float s_wt[BM];

    int tid = threadIdx.x;
    if (tid < BM) {
        s_tok[tid] = g_tok[e * CAP + m_base + tid];
        s_wt[tid]  = g_wt[e * CAP + m_base + tid];
    }
    __syncthreads();

    // Prologue: chunk 0 into buffer 0
    load_tiles(xin, W, s_tok, As[0], Bs[0], n_base, 0, tid);
    cp_commit();

    int warp = tid >> 5;
    int lane = tid & 31;
    int wm   = (warp >> 2) * 64;   // warp row offset (2 warp-rows)
    int wn   = (warp & 3) * 32;    // warp col offset (4 warp-cols)
    int gid  = lane >> 2;
    int tg   = lane & 3;

    float acc[4][4][4];
    #pragma unroll
    for (int mi = 0; mi < 4; mi++)
        #pragma unroll
        for (int ni = 0; ni < 4; ni++)
            #pragma unroll
            for (int r = 0; r < 4; r++) acc[mi][ni][r] = 0.f;

    const int NCHUNK = HDIM / KC;   // 32
    for (int kc = 0; kc < NCHUNK; kc++) {
        int buf = kc & 1;
        if (kc + 1 < NCHUNK) {
            load_tiles(xin, W, s_tok, As[buf ^ 1], Bs[buf ^ 1], n_base, (kc + 1) * KC, tid);
            cp_commit();
            cp_wait1();
        } else {
            cp_wait0();
        }
        __syncthreads();

        #pragma unroll
        for (int ks = 0; ks < 4; ks++) {
            int kb = ks * 8;
            // tf32x3 fragments: hi and lo halves of A and B
            uint32_t afh[4][4], afl[4][4], bfh[4][2], bfl[4][2];
            #pragma unroll
            for (int mi = 0; mi < 4; mi++) {
                int r = wm + mi * 16 + gid;
                f2tf_pair(As[buf][r][kb + tg],         afh[mi][0], afl[mi][0]);
                f2tf_pair(As[buf][r + 8][kb + tg],     afh[mi][1], afl[mi][1]);
                f2tf_pair(As[buf][r][kb + tg + 4],     afh[mi][2], afl[mi][2]);
                f2tf_pair(As[buf][r + 8][kb + tg + 4], afh[mi][3], afl[mi][3]);
            }
            #pragma unroll
            for (int ni = 0; ni < 4; ni++) {
                int cn = wn + ni * 8 + gid;
                f2tf_pair(Bs[buf][cn][kb + tg],     bfh[ni][0], bfl[ni][0]);
                f2tf_pair(Bs[buf][cn][kb + tg + 4], bfh[ni][1], bfl[ni][1]);
            }
            // Sweeps; dependent hits on one acc are 16 independent MMAs apart.
            #pragma unroll
            for (int mi = 0; mi < 4; mi++)
                #pragma unroll
                for (int ni = 0; ni < 4; ni++)
                    mma_tf32(acc[mi][ni], afh[mi], bfh[ni]);
            #pragma unroll
            for (int mi = 0; mi < 4; mi++)
                #pragma unroll
                for (int ni = 0; ni < 4; ni++)
                    mma_tf32(acc[mi][ni], afl[mi], bfh[ni]);
            if (sweeps3) {
                #pragma unroll
                for (int mi = 0; mi < 4; mi++)
                    #pragma unroll
                    for (int ni = 0; ni < 4; ni++)
                        mma_tf32(acc[mi][ni], afh[mi], bfl[ni]);
            }
        }
        __syncthreads();
    }

    // Epilogue: bias + PReLU + gate weight, scatter to pair buffer.
    const float* ebp = eb + (size_t)e * HDIM;
    const float* plp = pl + (size_t)e * HDIM;
    const float* prp = pr + (size_t)e * HDIM;
    const float* ppp = pp + (size_t)e * HDIM;
    const float* pbp = pb + (size_t)e * HDIM;

    #pragma unroll
    for (int ni = 0; ni < 4; ni++) {
        int o = n_base + wn + ni * 8 + 2 * tg;
        float2 e2 = *reinterpret_cast<const float2*>(ebp + o);
        float2 l2 = *reinterpret_cast<const float2*>(plp + o);
        float2 r2 = *reinterpret_cast<const float2*>(prp + o);
        float2 p2 = *reinterpret_cast<const float2*>(ppp + o);
        float2 b2 = *reinterpret_cast<const float2*>(pbp + o);
        #pragma unroll
        for (int mi = 0; mi < 4; mi++) {
            #pragma unroll
            for (int h = 0; h < 2; h++) {
                int r    = wm + mi * 16 + gid + h * 8;
                int slot = m_base + r;
                if (slot < cnt) {
                    int   packed = s_tok[r];
                    float w      = s_wt[r];
                    float y0 = acc[mi][ni][h * 2 + 0] + e2.x;
                    float d0 = y0 - p2.x;
                    float a0 = b2.x + (d0 >= 0.f ? d0 * r2.x : d0 * l2.x);
                    float y1 = acc[mi][ni][h * 2 + 1] + e2.y;
                    float d1 = y1 - p2.y;
                    float a1 = b2.y + (d1 >= 0.f ? d1 * r2.y : d1 * l2.y);
                    float2 out2 = make_float2(w * a0, w * a1);
                    *reinterpret_cast<float2*>(&g_pair[(size_t)packed * HDIM + o]) = out2;
                }
            }
        }
    }
}

// ---------------------------------------------------------------------------
// Kernel 3: combine the two weighted expert outputs per token (float4).
// ---------------------------------------------------------------------------
__global__ __launch_bounds__(256) void combine_kernel(int layer, float* __restrict__ out_ext) {
    float* dst = (layer == 0) ? g_act : out_ext;
    size_t i    = (size_t)blockIdx.x * blockDim.x + threadIdx.x;  // over B*H/4
    size_t elem = i * 4;
    size_t b    = elem >> 10;          // / HDIM
    size_t o    = elem & (HDIM - 1);
    float4 p0 = *reinterpret_cast<const float4*>(&g_pair[b * 2 * HDIM + o]);
    float4 p1 = *reinterpret_cast<const float4*>(&g_pair[b * 2 * HDIM + HDIM + o]);
    float4 r  = make_float4(p0.x + p1.x, p0.y + p1.y, p0.z + p1.z, p0.w + p1.w);
    *reinterpret_cast<float4*>(&dst[elem]) = r;
}

// ---------------------------------------------------------------------------
// Launch
// ---------------------------------------------------------------------------
extern "C" void kernel_launch(void* const* d_in, const int* in_sizes, int n_in,
                              void* d_out, int out_size) {
    const float* X  = (const float*)d_in[0];
    const float* gw = (const float*)d_in[1];
    const float* gb = (const float*)d_in[2];
    const float* ew = (const float*)d_in[3];
    const float* eb = (const float*)d_in[4];
    const float* pl = (const float*)d_in[5];
    const float* pr = (const float*)d_in[6];
    const float* pp = (const float*)d_in[7];
    const float* pb = (const float*)d_in[8];
    float* out = (float*)d_out;

    for (int d = 0; d < DEPTH; d++) {
        const float* gw_d = gw + (size_t)d * NEXP * HDIM;
        const float* gb_d = gb + (size_t)d * NEXP;
        const float* ew_d = ew + (size_t)d * NEXP * HDIM * HDIM;
        const float* eb_d = eb + (size_t)d * NEXP * HDIM;
        const float* pl_d = pl + (size_t)d * NEXP * HDIM;
        const float* pr_d = pr + (size_t)d * NEXP * HDIM;
        const float* pp_d = pp + (size_t)d * NEXP * HDIM;
        const float* pb_d = pb + (size_t)d * NEXP * HDIM;

        int sweeps3 = (d == 0) ? 1 : 0;   // layer 0 feeds routing: full tf32x3;
                                          // final layer: tf32x2 (~2.4e-4 rel, safe)
        reset_kernel<<<1, 32>>>();
        gate_kernel<<<NTOK / 8, 256>>>(d, X, gw_d, gb_d);
        dim3 grid(HDIM / BN, CAP / BM, NEXP);   // (8, 32, 16); empty m-tiles exit fast
        expert_gemm_kernel<<<grid, NTHREADS>>>(d, sweeps3, X, ew_d, eb_d,
                                               pl_d, pr_d, pp_d, pb_d);
        combine_kernel<<<(NTOK * HDIM / 4) / 256, 256>>>(d, out);
    }
}

// round 17
// speedup vs baseline: 1.5149x; 1.5149x over previous
#include <cuda_runtime.h>
#include <cstdint>

// Problem constants
#define DEPTH 2
#define NEXP  16
#define HDIM  1024
#define NTOK  8192
#define CAP   4096      // per-expert slot capacity (mean occupancy 1024)

// GEMM tile config
#define BM 128
#define BN 128
#define KC 32           // K floats per chunk (128B rows)
#define NTHREADS 256
#define SPAD 40         // smem row stride in floats; bank=(8*gid+2*tg)%32 conflict-free LDS.64

// Dynamic smem layout for the GEMM kernel (bytes)
#define SM_TOK  0                     // int[128]
#define SM_WT   512                   // float[128]
#define SM_AS   1024                  // float[2][BM][SPAD] = 40960
#define SM_BS   (SM_AS + 2 * BM * SPAD * 4)
#define SM_GEMM (SM_BS + 2 * BN * SPAD * 4)   // 82944 B

// ---------------------------------------------------------------------------
// Device-global scratch (no allocations allowed in kernel_launch)
// ---------------------------------------------------------------------------
__device__ float g_act[(size_t)NTOK * HDIM];          // layer-0 output activations
__device__ float g_pair[(size_t)NTOK * 2 * HDIM];     // per-assignment expert outputs
__device__ int   g_cnt[NEXP];
__device__ int   g_tok[NEXP * CAP];                   // packed token*2 + k
__device__ float g_wt[NEXP * CAP];                    // softmax gate weight per assignment

// ---------------------------------------------------------------------------
// Small PTX helpers
// ---------------------------------------------------------------------------
__device__ __forceinline__ uint32_t bf16x2_of(float vy, float vx) {
    // packed.lo = vx, packed.hi = vy
    uint32_t r;
    asm("cvt.rn.bf16x2.f32 %0, %1, %2;" : "=r"(r) : "f"(vy), "f"(vx));
    return r;
}

// bf16x3 split of a float2: h2 = packed bf16 hi parts, l2 = packed bf16 of (v - hi)
__device__ __forceinline__ void bfsplit(float2 v, uint32_t& h2, uint32_t& l2) {
    h2 = bf16x2_of(v.y, v.x);
    float hx = __uint_as_float(h2 << 16);
    float hy = __uint_as_float(h2 & 0xFFFF0000u);
    l2 = bf16x2_of(v.y - hy, v.x - hx);
}

__device__ __forceinline__ void mma_bf16(float* d, const uint32_t* a, const uint32_t* b) {
    asm volatile(
        "mma.sync.aligned.m16n8k16.row.col.f32.bf16.bf16.f32 "
        "{%0,%1,%2,%3}, {%4,%5,%6,%7}, {%8,%9}, {%0,%1,%2,%3};"
        : "+f"(d[0]), "+f"(d[1]), "+f"(d[2]), "+f"(d[3])
        : "r"(a[0]), "r"(a[1]), "r"(a[2]), "r"(a[3]), "r"(b[0]), "r"(b[1]));
}

__device__ __forceinline__ void cp16(uint32_t smem_dst, const void* gsrc) {
    asm volatile("cp.async.cg.shared.global [%0], [%1], 16;" :: "r"(smem_dst), "l"(gsrc));
}
__device__ __forceinline__ void cp_commit() { asm volatile("cp.async.commit_group;"); }
__device__ __forceinline__ void cp_wait1()  { asm volatile("cp.async.wait_group 1;"); }
__device__ __forceinline__ void cp_wait0()  { asm volatile("cp.async.wait_group 0;"); }

__device__ __forceinline__ uint32_t smem_u32(const void* p) {
    uint32_t a;
    asm("{ .reg .u64 t; cvta.to.shared.u64 t, %1; cvt.u32.u64 %0, t; }" : "=r"(a) : "l"(p));
    return a;
}

// ---------------------------------------------------------------------------
// Kernel 0: reset per-expert counters (per layer)
// ---------------------------------------------------------------------------
__global__ void reset_kernel() {
    if (threadIdx.x < NEXP) g_cnt[threadIdx.x] = 0;
}

// ---------------------------------------------------------------------------
// Kernel 1: gating — logits (fp32 FFMA), top-2, softmax, routing lists.
// ---------------------------------------------------------------------------
__global__ __launch_bounds__(256) void gate_kernel(
    int layer,
    const float* __restrict__ Xext,
    const float* __restrict__ gw,   // layer-offset: [NEXP, HDIM]
    const float* __restrict__ gb)   // layer-offset: [NEXP]
{
    const float* x = (layer == 0) ? Xext : g_act;

    __shared__ float4 sx4[8 * (HDIM / 4)];   // 8 tokens x 256 float4 = 32 KB

    int tid = threadIdx.x;
    const float4* x4 = reinterpret_cast<const float4*>(x);
    #pragma unroll
    for (int i = tid; i < 8 * (HDIM / 4); i += 256)
        sx4[i] = x4[(size_t)blockIdx.x * (8 * HDIM / 4) + i];
    __syncthreads();

    int wid  = tid >> 5;
    int lane = tid & 31;
    int b    = blockIdx.x * 8 + wid;

    const float4* gw4 = reinterpret_cast<const float4*>(gw);
    float G[NEXP];
    #pragma unroll
    for (int e = 0; e < NEXP; e++) {
        float acc = 0.f;
        #pragma unroll
        for (int j = 0; j < 8; j++) {
            float4 xv = sx4[wid * 256 + j * 32 + lane];
            float4 wv = gw4[e * 256 + j * 32 + lane];
            acc += xv.x * wv.x + xv.y * wv.y + xv.z * wv.z + xv.w * wv.w;
        }
        #pragma unroll
        for (int off = 16; off; off >>= 1)
            acc += __shfl_xor_sync(0xFFFFFFFFu, acc, off);
        G[e] = acc + gb[e];
    }

    if (lane == 0) {
        // top-2 with lowest-index tie-break (strict >), matching jax top_k
        int e0 = 0;
        #pragma unroll
        for (int e = 1; e < NEXP; e++) if (G[e] > G[e0]) e0 = e;
        int e1 = (e0 == 0) ? 1 : 0;
        #pragma unroll
        for (int e = 0; e < NEXP; e++) if (e != e0 && G[e] > G[e1]) e1 = e;

        float v0 = G[e0], v1 = G[e1];
        float z1 = expf(v1 - v0);          // v0 >= v1 -> stable
        float s  = 1.f + z1;
        float w0 = 1.f / s;
        float w1 = z1 / s;

        int p0 = atomicAdd(&g_cnt[e0], 1);
        if (p0 < CAP) { g_tok[e0 * CAP + p0] = b * 2 + 0; g_wt[e0 * CAP + p0] = w0; }
        int p1 = atomicAdd(&g_cnt[e1], 1);
        if (p1 < CAP) { g_tok[e1 * CAP + p1] = b * 2 + 1; g_wt[e1 * CAP + p1] = w1; }
    }
}

// ---------------------------------------------------------------------------
// Kernel 2: grouped expert GEMM — bf16x3 emulated-fp32 via mma.sync m16n8k16
//           (hi*hi + lo*hi + hi*lo; fp32 accum; rel err ~1e-5)
//           + bias + PReLU + gate weight epilogue.
// ---------------------------------------------------------------------------
__device__ __forceinline__ void load_tiles(
    const float* __restrict__ xin, const float* __restrict__ W,
    const int* s_tok, float* As, float* Bs,
    int n_base, int k0, int tid)
{
    #pragma unroll
    for (int it = 0; it < 4; it++) {
        int q   = tid + it * 256;          // 0..1023
        int row = q >> 3;                  // 0..127
        int cc  = (q & 7) * 4;             // 0..28
        const float* asrc = xin + (size_t)(s_tok[row] >> 1) * HDIM + k0 + cc;
        cp16(smem_u32(&As[row * SPAD + cc]), asrc);
        const float* bsrc = W + (size_t)(n_base + row) * HDIM + k0 + cc;
        cp16(smem_u32(&Bs[row * SPAD + cc]), bsrc);
    }
}

__global__ __launch_bounds__(NTHREADS, 1) void expert_gemm_kernel(
    int layer,
    const float* __restrict__ Xext,
    const float* __restrict__ ew,   // layer-offset: [NEXP, HDIM, HDIM] (o,i)
    const float* __restrict__ eb,   // layer-offset: [NEXP, HDIM]
    const float* __restrict__ pl,
    const float* __restrict__ pr,
    const float* __restrict__ pp,
    const float* __restrict__ pb)
{
    int e      = blockIdx.z;
    int m_base = blockIdx.y * BM;
    int n_base = blockIdx.x * BN;

    int cnt = g_cnt[e];
    if (cnt > CAP) cnt = CAP;
    if (m_base >= cnt) return;

    const float* xin = (layer == 0) ? Xext : g_act;
    const float* W   = ew + (size_t)e * HDIM * HDIM;

    extern __shared__ char smem[];
    int*   s_tok = reinterpret_cast<int*>(smem + SM_TOK);
    float* s_wt  = reinterpret_cast<float*>(smem + SM_WT);
    float* AsB   = reinterpret_cast<float*>(smem + SM_AS);   // [2][BM][SPAD]
    float* BsB   = reinterpret_cast<float*>(smem + SM_BS);   // [2][BN][SPAD]

    int tid = threadIdx.x;
    if (tid < BM) {
        s_tok[tid] = g_tok[e * CAP + m_base + tid];
        s_wt[tid]  = g_wt[e * CAP + m_base + tid];
    }
    __syncthreads();

    // Prologue: chunk 0 into buffer 0
    load_tiles(xin, W, s_tok, AsB, BsB, n_base, 0, tid);
    cp_commit();

    int warp = tid >> 5;
    int lane = tid & 31;
    int wm   = (warp >> 2) * 64;   // warp row offset (2 warp-rows)
    int wn   = (warp & 3) * 32;    // warp col offset (4 warp-cols)
    int gid  = lane >> 2;
    int tg   = lane & 3;

    float acc[4][4][4];
    #pragma unroll
    for (int mi = 0; mi < 4; mi++)
        #pragma unroll
        for (int ni = 0; ni < 4; ni++)
            #pragma unroll
            for (int r = 0; r < 4; r++) acc[mi][ni][r] = 0.f;

    const int NCHUNK = HDIM / KC;   // 32
    for (int kc = 0; kc < NCHUNK; kc++) {
        int buf = kc & 1;
        if (kc + 1 < NCHUNK) {
            load_tiles(xin, W, s_tok,
                       AsB + (buf ^ 1) * BM * SPAD, BsB + (buf ^ 1) * BN * SPAD,
                       n_base, (kc + 1) * KC, tid);
            cp_commit();
            cp_wait1();
        } else {
            cp_wait0();
        }
        __syncthreads();

        const float* As = AsB + buf * BM * SPAD;
        const float* Bs = BsB + buf * BN * SPAD;

        #pragma unroll
        for (int ks = 0; ks < 2; ks++) {
            int kb = ks * 16;
            // bf16x3 fragments (m16n8k16): each reg = 2 adjacent-k bf16
            uint32_t ah[4][4], al[4][4], bh[4][2], bl[4][2];
            #pragma unroll
            for (int mi = 0; mi < 4; mi++) {
                int r = wm + mi * 16 + gid;
                float2 v;
                v = *reinterpret_cast<const float2*>(&As[r * SPAD + kb + 2 * tg]);
                bfsplit(v, ah[mi][0], al[mi][0]);
                v = *reinterpret_cast<const float2*>(&As[(r + 8) * SPAD + kb + 2 * tg]);
                bfsplit(v, ah[mi][1], al[mi][1]);
                v = *reinterpret_cast<const float2*>(&As[r * SPAD + kb + 2 * tg + 8]);
                bfsplit(v, ah[mi][2], al[mi][2]);
                v = *reinterpret_cast<const float2*>(&As[(r + 8) * SPAD + kb + 2 * tg + 8]);
                bfsplit(v, ah[mi][3], al[mi][3]);
            }
            #pragma unroll
            for (int ni = 0; ni < 4; ni++) {
                int cn = wn + ni * 8 + gid;
                float2 v;
                v = *reinterpret_cast<const float2*>(&Bs[cn * SPAD + kb + 2 * tg]);
                bfsplit(v, bh[ni][0], bl[ni][0]);
                v = *reinterpret_cast<const float2*>(&Bs[cn * SPAD + kb + 2 * tg + 8]);
                bfsplit(v, bh[ni][1], bl[ni][1]);
            }
            // Three sweeps; dependent hits on one acc are 16 independent MMAs apart.
            #pragma unroll
            for (int mi = 0; mi < 4; mi++)
                #pragma unroll
                for (int ni = 0; ni < 4; ni++)
                    mma_bf16(acc[mi][ni], ah[mi], bh[ni]);
            #pragma unroll
            for (int mi = 0; mi < 4; mi++)
                #pragma unroll
                for (int ni = 0; ni < 4; ni++)
                    mma_bf16(acc[mi][ni], al[mi], bh[ni]);
            #pragma unroll
            for (int mi = 0; mi < 4; mi++)
                #pragma unroll
                for (int ni = 0; ni < 4; ni++)
                    mma_bf16(acc[mi][ni], ah[mi], bl[ni]);
        }
        __syncthreads();
    }

    // Epilogue: bias + PReLU + gate weight, scatter to pair buffer.
    const float* ebp = eb + (size_t)e * HDIM;
    const float* plp = pl + (size_t)e * HDIM;
    const float* prp = pr + (size_t)e * HDIM;
    const float* ppp = pp + (size_t)e * HDIM;
    const float* pbp = pb + (size_t)e * HDIM;

    #pragma unroll
    for (int ni = 0; ni < 4; ni++) {
        int o = n_base + wn + ni * 8 + 2 * tg;
        float2 e2 = *reinterpret_cast<const float2*>(ebp + o);
        float2 l2 = *reinterpret_cast<const float2*>(plp + o);
        float2 r2 = *reinterpret_cast<const float2*>(prp + o);
        float2 p2 = *reinterpret_cast<const float2*>(ppp + o);
        float2 b2 = *reinterpret_cast<const float2*>(pbp + o);
        #pragma unroll
        for (int mi = 0; mi < 4; mi++) {
            #pragma unroll
            for (int h = 0; h < 2; h++) {
                int r    = wm + mi * 16 + gid + h * 8;
                int slot = m_base + r;
                if (slot < cnt) {
                    int   packed = s_tok[r];
                    float w      = s_wt[r];
                    float y0 = acc[mi][ni][h * 2 + 0] + e2.x;
                    float d0 = y0 - p2.x;
                    float a0 = b2.x + (d0 >= 0.f ? d0 * r2.x : d0 * l2.x);
                    float y1 = acc[mi][ni][h * 2 + 1] + e2.y;
                    float d1 = y1 - p2.y;
                    float a1 = b2.y + (d1 >= 0.f ? d1 * r2.y : d1 * l2.y);
                    float2 out2 = make_float2(w * a0, w * a1);
                    *reinterpret_cast<float2*>(&g_pair[(size_t)packed * HDIM + o]) = out2;
                }
            }
        }
    }
}

// ---------------------------------------------------------------------------
// Kernel 3: combine the two weighted expert outputs per token (float4).
// ---------------------------------------------------------------------------
__global__ __launch_bounds__(256) void combine_kernel(int layer, float* __restrict__ out_ext) {
    float* dst = (layer == 0) ? g_act : out_ext;
    size_t i    = (size_t)blockIdx.x * blockDim.x + threadIdx.x;  // over B*H/4
    size_t elem = i * 4;
    size_t b    = elem >> 10;          // / HDIM
    size_t o    = elem & (HDIM - 1);
    float4 p0 = *reinterpret_cast<const float4*>(&g_pair[b * 2 * HDIM + o]);
    float4 p1 = *reinterpret_cast<const float4*>(&g_pair[b * 2 * HDIM + HDIM + o]);
    float4 r  = make_float4(p0.x + p1.x, p0.y + p1.y, p0.z + p1.z, p0.w + p1.w);
    *reinterpret_cast<float4*>(&dst[elem]) = r;
}

// ---------------------------------------------------------------------------
// Launch
// ---------------------------------------------------------------------------
extern "C" void kernel_launch(void* const* d_in, const int* in_sizes, int n_in,
                              void* d_out, int out_size) {
    const float* X  = (const float*)d_in[0];
    const float* gw = (const float*)d_in[1];
    const float* gb = (const float*)d_in[2];
    const float* ew = (const float*)d_in[3];
    const float* eb = (const float*)d_in[4];
    const float* pl = (const float*)d_in[5];
    const float* pr = (const float*)d_in[6];
    const float* pp = (const float*)d_in[7];
    const float* pb = (const float*)d_in[8];
    float* out = (float*)d_out;

    cudaFuncSetAttribute(expert_gemm_kernel,
                         cudaFuncAttributeMaxDynamicSharedMemorySize, SM_GEMM);

    for (int d = 0; d < DEPTH; d++) {
        const float* gw_d = gw + (size_t)d * NEXP * HDIM;
        const float* gb_d = gb + (size_t)d * NEXP;
        const float* ew_d = ew + (size_t)d * NEXP * HDIM * HDIM;
        const float* eb_d = eb + (size_t)d * NEXP * HDIM;
        const float* pl_d = pl + (size_t)d * NEXP * HDIM;
        const float* pr_d = pr + (size_t)d * NEXP * HDIM;
        const float* pp_d = pp + (size_t)d * NEXP * HDIM;
        const float* pb_d = pb + (size_t)d * NEXP * HDIM;

        reset_kernel<<<1, 32>>>();
        gate_kernel<<<NTOK / 8, 256>>>(d, X, gw_d, gb_d);
        dim3 grid(HDIM / BN, CAP / BM, NEXP);   // (8, 32, 16); empty m-tiles exit fast
        expert_gemm_kernel<<<grid, NTHREADS, SM_GEMM>>>(d, X, ew_d, eb_d,
                                                        pl_d, pr_d, pp_d, pb_d);
        combine_kernel<<<(NTOK * HDIM / 4) / 256, 256>>>(d, out);
    }
}